// round 2
// baseline (speedup 1.0000x reference)
#include <cuda_runtime.h>
#include <math.h>
#include <float.h>

// Problem constants
#define BSZ 2
#define SEQ 2048
#define NH  16
#define HD  64
#define BM  128         // query tile
#define BN  64          // key tile
#define NT  256
#define SM_SCALE 0.125f

// Dynamic smem layout (float offsets)
#define QT_OFF 0        // Q transposed+swizzled: [64 c][128 r]      = 32KB
#define KP_OFF 8192     // K dup-pairs (then Pt): [64 kj][128]       = 32KB
#define VD_OFF 16384    // V dup-pairs:           [64 kj][128]       = 32KB
#define SMEM_BYTES (24576 * 4)

// ---- f32x2 packed helpers (ptxas won't emit FFMA2 from C++) ----
__device__ __forceinline__ unsigned long long pk2(float lo, float hi) {
    unsigned long long r;
    asm("mov.b64 %0, {%1,%2};" : "=l"(r) : "f"(lo), "f"(hi));
    return r;
}
__device__ __forceinline__ void upk2(unsigned long long p, float& lo, float& hi) {
    asm("mov.b64 {%0,%1}, %2;" : "=f"(lo), "=f"(hi) : "l"(p));
}
__device__ __forceinline__ void fma2(unsigned long long& d, unsigned long long a,
                                     unsigned long long b) {
    asm("fma.rn.f32x2 %0, %1, %2, %0;" : "+l"(d) : "l"(a), "l"(b));
}
__device__ __forceinline__ unsigned long long mul2(unsigned long long a,
                                                   unsigned long long b) {
    unsigned long long r;
    asm("mul.rn.f32x2 %0, %1, %2;" : "=l"(r) : "l"(a), "l"(b));
    return r;
}

// Q-transpose swizzle: multiple of 4 (preserves float4 reads), 8-way bank spread
// on the transposing store. Reads are 16-lane broadcasts (conflict-immune).
__device__ __forceinline__ int qswz(int c) { return 4 * ((c + (c >> 2)) & 7); }

__global__ __launch_bounds__(NT, 2)
void fa2_kernel(const float* __restrict__ q, const float* __restrict__ k,
                const float* __restrict__ v, const float* __restrict__ bias,
                const int* __restrict__ m, float* __restrict__ out)
{
    extern __shared__ float smf[];
    float* Qt = smf + QT_OFF;
    float* KP = smf + KP_OFF;   // K dup-pairs during S; Pt during PV
    float* Vd = smf + VD_OFF;

    const int tid = threadIdx.x;
    const int tx  = tid & 15;
    const int ty  = tid >> 4;          // 16 values; thread owns rows 8*ty..8*ty+7
    const int qt  = gridDim.x - 1 - blockIdx.x;  // heavy (high-qt) blocks first
    const int h   = blockIdx.y;
    const int b   = blockIdx.z;
    const int q0  = qt * BM;

    const int* mb = m + b * SEQ;

    // Per-row segment starts (m sorted ascending -> lower_bound)
    int seg_start[8];
#pragma unroll
    for (int ii = 0; ii < 8; ii++) {
        int qg  = q0 + 8 * ty + ii;
        int tgt = mb[qg];
        int lo = 0, hi = qg;
        while (lo < hi) { int mid = (lo + hi) >> 1; if (mb[mid] < tgt) lo = mid + 1; else hi = mid; }
        seg_start[ii] = lo;
    }
    int kt0;
    {
        int tgt = mb[q0];
        int lo = 0, hi = q0;
        while (lo < hi) { int mid = (lo + hi) >> 1; if (mb[mid] < tgt) lo = mid + 1; else hi = mid; }
        kt0 = lo >> 6;
    }
    const int ktN = (q0 + BM - 1) >> 6;   // last causal key tile = 2*qt+1

    const int rs = NH * HD;  // 1024 floats between tokens
    const float* qb = q    + ((long long)(b * SEQ + q0) * NH + h) * HD;
    const float* kb = k    + ((long long)(b * SEQ) * NH + h) * HD;
    const float* vb = v    + ((long long)(b * SEQ) * NH + h) * HD;
    const float* bb = bias + (((long long)b * NH + h) * SEQ + q0) * SEQ;

    // ---- Load Q transposed + swizzled (once per block) ----
#pragma unroll
    for (int e = tid; e < BM * 16; e += NT) {
        int r = e >> 4, cg = e & 15;
        float4 t = *(const float4*)(qb + (long long)r * rs + 4 * cg);
        int c0 = 4 * cg;
        Qt[(c0 + 0) * BM + (r ^ qswz(c0 + 0))] = t.x;
        Qt[(c0 + 1) * BM + (r ^ qswz(c0 + 1))] = t.y;
        Qt[(c0 + 2) * BM + (r ^ qswz(c0 + 2))] = t.z;
        Qt[(c0 + 3) * BM + (r ^ qswz(c0 + 3))] = t.w;
    }

    unsigned long long o2[4][4];   // [row-pair u][col jj]: (o[r0],o[r1]) packed
    float mi[8], li[8];
#pragma unroll
    for (int u = 0; u < 4; u++)
#pragma unroll
        for (int jj = 0; jj < 4; jj++) o2[u][jj] = 0ull;
#pragma unroll
    for (int ii = 0; ii < 8; ii++) { mi[ii] = -FLT_MAX; li[ii] = 0.f; }

    for (int kt = kt0; kt <= ktN; kt++) {
        const int k0 = kt * BN;
        __syncthreads();   // prev-iter Pt/Vd reads complete

        // ---- Load K as dup-pairs (swizzled) and V as dup-pairs (plain) ----
#pragma unroll
        for (int e = tid; e < BN * 16; e += NT) {
            int r = e >> 4, cg = e & 15;
            int rl = r & 15;
            float4 kk = *(const float4*)(kb + (long long)(k0 + r) * rs + 4 * cg);
            *(float2*)&KP[r * 128 + 2 * ((4 * cg + 0) ^ rl)] = make_float2(kk.x, kk.x);
            *(float2*)&KP[r * 128 + 2 * ((4 * cg + 1) ^ rl)] = make_float2(kk.y, kk.y);
            *(float2*)&KP[r * 128 + 2 * ((4 * cg + 2) ^ rl)] = make_float2(kk.z, kk.z);
            *(float2*)&KP[r * 128 + 2 * ((4 * cg + 3) ^ rl)] = make_float2(kk.w, kk.w);
            float4 vv = *(const float4*)(vb + (long long)(k0 + r) * rs + 4 * cg);
            *(float2*)&Vd[r * 128 + 8 * cg + 0] = make_float2(vv.x, vv.x);
            *(float2*)&Vd[r * 128 + 8 * cg + 2] = make_float2(vv.y, vv.y);
            *(float2*)&Vd[r * 128 + 8 * cg + 4] = make_float2(vv.z, vv.z);
            *(float2*)&Vd[r * 128 + 8 * cg + 6] = make_float2(vv.w, vv.w);
        }
        __syncthreads();

        // ---- S = Q @ K^T : 8x4 per thread, all FFMA2 ----
        unsigned long long s2[4][4];
#pragma unroll
        for (int u = 0; u < 4; u++)
#pragma unroll
            for (int jj = 0; jj < 4; jj++) s2[u][jj] = 0ull;

        const float* kb0 = KP + (tx +  0) * 128;
        const float* kb1 = KP + (tx + 16) * 128;
        const float* kb2 = KP + (tx + 32) * 128;
        const float* kb3 = KP + (tx + 48) * 128;

#pragma unroll 8
        for (int c = 0; c < 64; c++) {
            int sw  = qswz(c);
            ulonglong2 qa = *(const ulonglong2*)&Qt[c * BM + ((8 * ty)     ^ sw)];
            ulonglong2 qc = *(const ulonglong2*)&Qt[c * BM + ((8 * ty + 4) ^ sw)];
            int off = 2 * (c ^ tx);   // shared across all jj: (tx+16jj)&15 == tx
            unsigned long long k0v = *(const unsigned long long*)(kb0 + off);
            unsigned long long k1v = *(const unsigned long long*)(kb1 + off);
            unsigned long long k2v = *(const unsigned long long*)(kb2 + off);
            unsigned long long k3v = *(const unsigned long long*)(kb3 + off);
            fma2(s2[0][0], qa.x, k0v); fma2(s2[0][1], qa.x, k1v);
            fma2(s2[0][2], qa.x, k2v); fma2(s2[0][3], qa.x, k3v);
            fma2(s2[1][0], qa.y, k0v); fma2(s2[1][1], qa.y, k1v);
            fma2(s2[1][2], qa.y, k2v); fma2(s2[1][3], qa.y, k3v);
            fma2(s2[2][0], qc.x, k0v); fma2(s2[2][1], qc.x, k1v);
            fma2(s2[2][2], qc.x, k2v); fma2(s2[2][3], qc.x, k3v);
            fma2(s2[3][0], qc.y, k0v); fma2(s2[3][1], qc.y, k1v);
            fma2(s2[3][2], qc.y, k2v); fma2(s2[3][3], qc.y, k3v);
        }

        __syncthreads();   // all warps done reading KP before Pt overwrite

        // ---- mask + bias + online softmax per row-pair; write Pt ----
#pragma unroll
        for (int u = 0; u < 4; u++) {
            float s0[4], s1[4];
#pragma unroll
            for (int jj = 0; jj < 4; jj++) upk2(s2[u][jj], s0[jj], s1[jj]);

            float p0[4], p1[4], scl0, scl1;
            // --- row 2u ---
            {
                const int ii = 2 * u;
                const int qg = q0 + 8 * ty + ii;
                const float* brow = bb + (long long)(8 * ty + ii) * SEQ + k0;
                float rmax = -FLT_MAX;
#pragma unroll
                for (int jj = 0; jj < 4; jj++) {
                    int kg = k0 + tx + 16 * jj;
                    float t = -FLT_MAX;
                    if ((kg <= qg) && (kg >= seg_start[ii]))
                        t = s0[jj] * SM_SCALE + brow[tx + 16 * jj];
                    p0[jj] = t;
                    rmax = fmaxf(rmax, t);
                }
#pragma unroll
                for (int off = 8; off >= 1; off >>= 1)
                    rmax = fmaxf(rmax, __shfl_xor_sync(0xffffffffu, rmax, off));
                float mnew = fmaxf(mi[ii], rmax);
                scl0 = __expf(mi[ii] - mnew);
                float rsum = 0.f;
#pragma unroll
                for (int jj = 0; jj < 4; jj++) {
                    float pv = (p0[jj] == -FLT_MAX) ? 0.f : __expf(p0[jj] - mnew);
                    p0[jj] = pv; rsum += pv;
                }
#pragma unroll
                for (int off = 8; off >= 1; off >>= 1)
                    rsum += __shfl_xor_sync(0xffffffffu, rsum, off);
                li[ii] = li[ii] * scl0 + rsum;
                mi[ii] = mnew;
            }
            // --- row 2u+1 ---
            {
                const int ii = 2 * u + 1;
                const int qg = q0 + 8 * ty + ii;
                const float* brow = bb + (long long)(8 * ty + ii) * SEQ + k0;
                float rmax = -FLT_MAX;
#pragma unroll
                for (int jj = 0; jj < 4; jj++) {
                    int kg = k0 + tx + 16 * jj;
                    float t = -FLT_MAX;
                    if ((kg <= qg) && (kg >= seg_start[ii]))
                        t = s1[jj] * SM_SCALE + brow[tx + 16 * jj];
                    p1[jj] = t;
                    rmax = fmaxf(rmax, t);
                }
#pragma unroll
                for (int off = 8; off >= 1; off >>= 1)
                    rmax = fmaxf(rmax, __shfl_xor_sync(0xffffffffu, rmax, off));
                float mnew = fmaxf(mi[ii], rmax);
                scl1 = __expf(mi[ii] - mnew);
                float rsum = 0.f;
#pragma unroll
                for (int jj = 0; jj < 4; jj++) {
                    float pv = (p1[jj] == -FLT_MAX) ? 0.f : __expf(p1[jj] - mnew);
                    p1[jj] = pv; rsum += pv;
                }
#pragma unroll
                for (int off = 8; off >= 1; off >>= 1)
                    rsum += __shfl_xor_sync(0xffffffffu, rsum, off);
                li[ii] = li[ii] * scl1 + rsum;
                mi[ii] = mnew;
            }

            // rescale running O pair
            unsigned long long sc = pk2(scl0, scl1);
#pragma unroll
            for (int jj = 0; jj < 4; jj++) o2[u][jj] = mul2(o2[u][jj], sc);

            // write Pt (transposed, pair-swizzled): Pt[kj][r ^ 2*(kj&15)]
            int rp = (8 * ty + 2 * u) ^ (2 * tx);   // kj&15 == tx for all jj
#pragma unroll
            for (int jj = 0; jj < 4; jj++)
                *(float2*)&KP[(tx + 16 * jj) * 128 + rp] = make_float2(p0[jj], p1[jj]);
        }
        __syncthreads();

        // ---- O += P @ V : all FFMA2, broadcast Pt reads, dup-V b-operands ----
        {
            const float* vrow = Vd + 2 * tx;
            const float* prow = KP;
            const int r0 = 8 * ty;
#pragma unroll 4
            for (int kj = 0; kj < 64; kj++) {
                int px = 2 * (kj & 15);
                unsigned long long pa = *(const unsigned long long*)&prow[(r0 + 0) ^ px];
                unsigned long long pb = *(const unsigned long long*)&prow[(r0 + 2) ^ px];
                unsigned long long pc = *(const unsigned long long*)&prow[(r0 + 4) ^ px];
                unsigned long long pd = *(const unsigned long long*)&prow[(r0 + 6) ^ px];
                unsigned long long v0 = *(const unsigned long long*)(vrow +  0);
                unsigned long long v1 = *(const unsigned long long*)(vrow + 32);
                unsigned long long v2 = *(const unsigned long long*)(vrow + 64);
                unsigned long long v3 = *(const unsigned long long*)(vrow + 96);
                fma2(o2[0][0], pa, v0); fma2(o2[0][1], pa, v1);
                fma2(o2[0][2], pa, v2); fma2(o2[0][3], pa, v3);
                fma2(o2[1][0], pb, v0); fma2(o2[1][1], pb, v1);
                fma2(o2[1][2], pb, v2); fma2(o2[1][3], pb, v3);
                fma2(o2[2][0], pc, v0); fma2(o2[2][1], pc, v1);
                fma2(o2[2][2], pc, v2); fma2(o2[2][3], pc, v3);
                fma2(o2[3][0], pd, v0); fma2(o2[3][1], pd, v1);
                fma2(o2[3][2], pd, v2); fma2(o2[3][3], pd, v3);
                vrow += 128;
                prow += 128;
            }
        }
    }

    // ---- epilogue: normalize and store ----
    float* ob = out + ((long long)(b * SEQ + q0) * NH + h) * HD;
#pragma unroll
    for (int u = 0; u < 4; u++) {
        float inv0 = 1.f / li[2 * u];
        float inv1 = 1.f / li[2 * u + 1];
        int r0 = 8 * ty + 2 * u;
#pragma unroll
        for (int jj = 0; jj < 4; jj++) {
            float f0, f1;
            upk2(o2[u][jj], f0, f1);
            ob[(long long)(r0)     * rs + tx + 16 * jj] = f0 * inv0;
            ob[(long long)(r0 + 1) * rs + tx + 16 * jj] = f1 * inv1;
        }
    }
}

extern "C" void kernel_launch(void* const* d_in, const int* in_sizes, int n_in,
                              void* d_out, int out_size)
{
    const float* q    = (const float*)d_in[0];
    const float* k    = (const float*)d_in[1];
    const float* v    = (const float*)d_in[2];
    const float* bias = (const float*)d_in[3];
    const int*   m    = (const int*)d_in[4];
    float* out = (float*)d_out;

    cudaFuncSetAttribute(fa2_kernel, cudaFuncAttributeMaxDynamicSharedMemorySize,
                         SMEM_BYTES);
    dim3 grid(SEQ / BM, NH, BSZ);   // 16 x 16 x 2 = 512 blocks
    fa2_kernel<<<grid, NT, SMEM_BYTES>>>(q, k, v, bias, m, out);
}